// round 2
// baseline (speedup 1.0000x reference)
#include <cuda_runtime.h>
#include <cuda_bf16.h>
#include <math.h>

#define N_NODES 100000
#define N_EDGES 1600000
#define D 128

// Scratch (allocation-free rule: __device__ globals).
// NOTE: these symbols are ONLY referenced from device code. Referencing them
// from host code yields the host shadow address (the Round-1 bug).
__device__ float g_agg[(size_t)N_NODES * D];   // 51.2 MB
__device__ float g_h[(size_t)N_NODES * D];     // 51.2 MB

__device__ __forceinline__ void red4(float* p, float4 v) {
    asm volatile("red.global.add.v4.f32 [%0], {%1,%2,%3,%4};"
                 :: "l"(p), "f"(v.x), "f"(v.y), "f"(v.z), "f"(v.w)
                 : "memory");
}

// ---------------------------------------------------------------------------
// Zero the aggregation buffer (float4 stores)
// ---------------------------------------------------------------------------
__global__ void zero_agg_kernel() {
    size_t i = (size_t)blockIdx.x * blockDim.x + threadIdx.x;
    const size_t n4 = (size_t)N_NODES * D / 4;
    if (i < n4) reinterpret_cast<float4*>(g_agg)[i] = make_float4(0.f, 0.f, 0.f, 0.f);
}

// ---------------------------------------------------------------------------
// Layer-1 scatter: g_agg[dst] += emb_table[cncpt_ids[src]]
// One warp per edge; lane handles one float4 (32 lanes * 16B = 512B row).
// ---------------------------------------------------------------------------
__global__ void scatter_emb_kernel(const int* __restrict__ cncpt,
                                   const int* __restrict__ src,
                                   const int* __restrict__ dst,
                                   const float* __restrict__ emb) {
    long long gid = (long long)blockIdx.x * blockDim.x + threadIdx.x;
    int e = (int)(gid >> 5);
    if (e >= N_EDGES) return;
    int lane = threadIdx.x & 31;
    int s = __ldg(src + e);
    int d = __ldg(dst + e);
    int c = __ldg(cncpt + s);
    float4 v = __ldg(reinterpret_cast<const float4*>(emb + (size_t)c * D) + lane);
    red4(g_agg + (size_t)d * D + lane * 4, v);
}

// ---------------------------------------------------------------------------
// Layer-2 scatter: g_agg[dst] += g_h[src]   (g_h is L2-resident, 51MB)
// ---------------------------------------------------------------------------
__global__ void scatter_h_kernel(const int* __restrict__ src,
                                 const int* __restrict__ dst) {
    long long gid = (long long)blockIdx.x * blockDim.x + threadIdx.x;
    int e = (int)(gid >> 5);
    if (e >= N_EDGES) return;
    int lane = threadIdx.x & 31;
    int s = __ldg(src + e);
    int d = __ldg(dst + e);
    float4 v = __ldg(reinterpret_cast<const float4*>(g_h + (size_t)s * D) + lane);
    red4(g_agg + (size_t)d * D + lane * 4, v);
}

// ---------------------------------------------------------------------------
// MLP: y = relu(x @ W^T + b), x = g_agg rows.
//   FINAL=false: writes y rows DIRECTLY to the g_h device symbol (device-side
//                symbol reference — correct address space).
//   FINAL=true : fuses out = sigmoid(dot(y, wout) + bout) -> d_out (param).
// 128 threads/block, thread t computes output feature t.
// W staged in shared with stride-132 padding (conflict-free float4 reads).
// 4 nodes batched per pass: each W shared-read feeds 16 FMAs (FMA-bound).
// Dynamic smem: 128*132 (W) + 4*128 (x) floats = 69632 B.
// ---------------------------------------------------------------------------
template <bool FINAL>
__global__ void __launch_bounds__(128) mlp_kernel(const float* __restrict__ W,
                                                  const float* __restrict__ b,
                                                  const float* __restrict__ wout,
                                                  const float* __restrict__ bout,
                                                  float* __restrict__ out) {
    extern __shared__ float sh[];
    float* Ws = sh;                 // [128][132]
    float* xs = sh + 128 * 132;     // [4][128]
    __shared__ float warp_sums[4][4];

    const int t = threadIdx.x;
    const int lane = t & 31;
    const int wid = t >> 5;

    // Stage W: Ws[j*132 + k] = W[j*128 + k]; coalesced global reads.
    for (int r = 0; r < D; r++)
        Ws[r * 132 + t] = __ldg(W + r * D + t);

    const float bt = __ldg(b + t);
    const float wo = FINAL ? __ldg(wout + t) : 0.f;
    const float bo = FINAL ? __ldg(bout) : 0.f;
    __syncthreads();

    const float4* wrow = reinterpret_cast<const float4*>(Ws + t * 132);
    const int ngroups = N_NODES / 4;   // 25000, exact

    for (int g = blockIdx.x; g < ngroups; g += gridDim.x) {
        const size_t base = (size_t)g * 4 * D;
        xs[t]       = g_agg[base + t];
        xs[t + 128] = g_agg[base + D + t];
        xs[t + 256] = g_agg[base + 2 * D + t];
        xs[t + 384] = g_agg[base + 3 * D + t];
        __syncthreads();

        float a0 = bt, a1 = bt, a2 = bt, a3 = bt;
        const float4* x0p = reinterpret_cast<const float4*>(xs);
        const float4* x1p = reinterpret_cast<const float4*>(xs + 128);
        const float4* x2p = reinterpret_cast<const float4*>(xs + 256);
        const float4* x3p = reinterpret_cast<const float4*>(xs + 384);
#pragma unroll 8
        for (int k4 = 0; k4 < 32; k4++) {
            float4 w  = wrow[k4];
            float4 x0 = x0p[k4];
            float4 x1 = x1p[k4];
            float4 x2 = x2p[k4];
            float4 x3 = x3p[k4];
            a0 = fmaf(w.x, x0.x, fmaf(w.y, x0.y, fmaf(w.z, x0.z, fmaf(w.w, x0.w, a0))));
            a1 = fmaf(w.x, x1.x, fmaf(w.y, x1.y, fmaf(w.z, x1.z, fmaf(w.w, x1.w, a1))));
            a2 = fmaf(w.x, x2.x, fmaf(w.y, x2.y, fmaf(w.z, x2.z, fmaf(w.w, x2.w, a2))));
            a3 = fmaf(w.x, x3.x, fmaf(w.y, x3.y, fmaf(w.z, x3.z, fmaf(w.w, x3.w, a3))));
        }
        a0 = fmaxf(a0, 0.f);
        a1 = fmaxf(a1, 0.f);
        a2 = fmaxf(a2, 0.f);
        a3 = fmaxf(a3, 0.f);

        if (!FINAL) {
            // Write directly to the device symbol g_h (valid in device code).
            g_h[base + t]         = a0;
            g_h[base + D + t]     = a1;
            g_h[base + 2 * D + t] = a2;
            g_h[base + 3 * D + t] = a3;
            __syncthreads();   // protect xs before next group's fill
        } else {
            float p0 = a0 * wo, p1 = a1 * wo, p2 = a2 * wo, p3 = a3 * wo;
#pragma unroll
            for (int o = 16; o; o >>= 1) {
                p0 += __shfl_down_sync(0xffffffffu, p0, o);
                p1 += __shfl_down_sync(0xffffffffu, p1, o);
                p2 += __shfl_down_sync(0xffffffffu, p2, o);
                p3 += __shfl_down_sync(0xffffffffu, p3, o);
            }
            if (lane == 0) {
                warp_sums[0][wid] = p0;
                warp_sums[1][wid] = p1;
                warp_sums[2][wid] = p2;
                warp_sums[3][wid] = p3;
            }
            __syncthreads();
            if (t < 4) {
                float s = warp_sums[t][0] + warp_sums[t][1] +
                          warp_sums[t][2] + warp_sums[t][3];
                out[g * 4 + t] = 1.f / (1.f + expf(-(s + bo)));
            }
            __syncthreads();
        }
    }
}

// ---------------------------------------------------------------------------
extern "C" void kernel_launch(void* const* d_in, const int* in_sizes, int n_in,
                              void* d_out, int out_size) {
    const int*   cncpt = (const int*)d_in[0];
    const int*   src   = (const int*)d_in[1];
    const int*   dst   = (const int*)d_in[2];
    const float* emb   = (const float*)d_in[3];
    const float* W1    = (const float*)d_in[4];
    const float* b1    = (const float*)d_in[5];
    const float* W2    = (const float*)d_in[6];
    const float* b2    = (const float*)d_in[7];
    const float* Wout  = (const float*)d_in[8];
    const float* bout  = (const float*)d_in[9];
    float* out = (float*)d_out;

    const int SMEM = (128 * 132 + 4 * 128) * sizeof(float);  // 69632 B
    cudaFuncSetAttribute(mlp_kernel<false>, cudaFuncAttributeMaxDynamicSharedMemorySize, SMEM);
    cudaFuncSetAttribute(mlp_kernel<true>,  cudaFuncAttributeMaxDynamicSharedMemorySize, SMEM);

    const int ZERO_BLOCKS    = (N_NODES * D / 4 + 255) / 256;                 // 12500
    const int SCATTER_BLOCKS = (int)(((long long)N_EDGES * 32 + 255) / 256);  // 200000
    const int MLP_GRID = 444;  // 3 blocks/SM * 148 SMs

    // Layer 1: agg = segsum(emb[cncpt[src]], dst); h = relu(agg @ W1^T + b1) -> g_h
    zero_agg_kernel<<<ZERO_BLOCKS, 256>>>();
    scatter_emb_kernel<<<SCATTER_BLOCKS, 256>>>(cncpt, src, dst, emb);
    mlp_kernel<false><<<MLP_GRID, 128, SMEM>>>(W1, b1, nullptr, nullptr, nullptr);

    // Layer 2: agg = segsum(h[src], dst); out = sigmoid(relu(agg@W2^T+b2) @ Wout^T + bout)
    zero_agg_kernel<<<ZERO_BLOCKS, 256>>>();
    scatter_h_kernel<<<SCATTER_BLOCKS, 256>>>(src, dst);
    mlp_kernel<true><<<MLP_GRID, 128, SMEM>>>(W2, b2, Wout, bout, out);

    (void)in_sizes; (void)n_in; (void)out_size;
}

// round 3
// speedup vs baseline: 1.6380x; 1.6380x over previous
#include <cuda_runtime.h>
#include <cuda_bf16.h>
#include <math.h>

#define N_NODES   100000
#define N_EDGES   1600000
#define D         128
#define SCAN_BS   1024
#define SCAN_NB   ((N_NODES + SCAN_BS - 1) / SCAN_BS)   // 98

// ---------------------------------------------------------------------------
// Scratch (__device__ globals; referenced ONLY from device code)
// ---------------------------------------------------------------------------
__device__ float g_x0 [(size_t)N_NODES * D];   // emb[cncpt[v]]      (51.2 MB)
__device__ float g_agg[(size_t)N_NODES * D];   // aggregation output (51.2 MB)
__device__ float g_h  [(size_t)N_NODES * D];   // layer-1 output     (51.2 MB)
__device__ float g_W1t[D * D];                 // W1 transposed [k][f]
__device__ float g_W2t[D * D];                 // W2 transposed [k][f]
__device__ int   g_counts [N_NODES];
__device__ int   g_excl   [N_NODES];
__device__ int   g_rowptr [N_NODES + 1];
__device__ int   g_cursor [N_NODES];
__device__ int   g_bsum   [SCAN_NB];
__device__ int   g_boff   [SCAN_NB];
__device__ int   g_csrsrc [N_EDGES];

// ---------------------------------------------------------------------------
// Weight transpose (once per call): g_Wt[k*128+f] = W[f*128+k]
// ---------------------------------------------------------------------------
__global__ void transpose_w_kernel(const float* __restrict__ W1,
                                   const float* __restrict__ W2) {
    int i = blockIdx.x * blockDim.x + threadIdx.x;  // 0..16383
    if (i >= D * D) return;
    int k = i >> 7, f = i & 127;
    g_W1t[i] = __ldg(W1 + f * D + k);
    g_W2t[i] = __ldg(W2 + f * D + k);
}

// ---------------------------------------------------------------------------
// CSR build: zero counts -> histogram -> 3-phase scan -> fill
// ---------------------------------------------------------------------------
__global__ void zero_counts_kernel() {
    int i = blockIdx.x * blockDim.x + threadIdx.x;
    if (i < N_NODES) g_counts[i] = 0;
}

__global__ void hist_kernel(const int* __restrict__ dst) {
    int e = blockIdx.x * blockDim.x + threadIdx.x;
    if (e < N_EDGES) atomicAdd(&g_counts[__ldg(dst + e)], 1);
}

__global__ void scan1_kernel() {   // per-block exclusive scan (Hillis-Steele)
    __shared__ int s[SCAN_BS];
    int t = threadIdx.x;
    int i = blockIdx.x * SCAN_BS + t;
    int v = (i < N_NODES) ? g_counts[i] : 0;
    s[t] = v;
    __syncthreads();
#pragma unroll
    for (int off = 1; off < SCAN_BS; off <<= 1) {
        int add = (t >= off) ? s[t - off] : 0;
        __syncthreads();
        s[t] += add;
        __syncthreads();
    }
    int incl = s[t];
    if (i < N_NODES) g_excl[i] = incl - v;
    if (t == SCAN_BS - 1) g_bsum[blockIdx.x] = incl;
}

__global__ void scan2_kernel() {   // tiny serial scan of 98 block sums
    if (threadIdx.x == 0 && blockIdx.x == 0) {
        int run = 0;
        for (int j = 0; j < SCAN_NB; j++) { g_boff[j] = run; run += g_bsum[j]; }
    }
}

__global__ void scan3_kernel() {
    int i = blockIdx.x * blockDim.x + threadIdx.x;
    if (i < N_NODES) {
        int rp = g_excl[i] + g_boff[i >> 10];
        g_rowptr[i] = rp;
        g_cursor[i] = rp;
    }
    if (i == 0) g_rowptr[N_NODES] = N_EDGES;
}

__global__ void fill_csr_kernel(const int* __restrict__ src,
                                const int* __restrict__ dst) {
    int e = blockIdx.x * blockDim.x + threadIdx.x;
    if (e >= N_EDGES) return;
    int d = __ldg(dst + e);
    int p = atomicAdd(&g_cursor[d], 1);
    g_csrsrc[p] = __ldg(src + e);
}

// ---------------------------------------------------------------------------
// Per-node embedding gather: g_x0[v] = emb[cncpt[v]]  (warp per node)
// ---------------------------------------------------------------------------
__global__ void gather_x0_kernel(const int* __restrict__ cncpt,
                                 const float* __restrict__ emb) {
    int node = (blockIdx.x * blockDim.x + threadIdx.x) >> 5;
    if (node >= N_NODES) return;
    int lane = threadIdx.x & 31;
    int c = __ldg(cncpt + node);
    float4 v = __ldg(reinterpret_cast<const float4*>(emb + (size_t)c * D) + lane);
    reinterpret_cast<float4*>(g_x0 + (size_t)node * D)[lane] = v;
}

// ---------------------------------------------------------------------------
// CSR gather-aggregation: g_agg[v] = sum_{e in row v} xin[csrsrc[e]]
// Warp per node, lane = one float4 of the 128-dim row. No atomics, no zeroing.
// ---------------------------------------------------------------------------
template <bool FIRST>
__global__ void __launch_bounds__(256) agg_kernel() {
    int node = (blockIdx.x * blockDim.x + threadIdx.x) >> 5;
    if (node >= N_NODES) return;
    int lane = threadIdx.x & 31;
    const float* __restrict__ xin = FIRST ? g_x0 : g_h;

    int beg = __ldg(g_rowptr + node);
    int end = __ldg(g_rowptr + node + 1);

    float4 a0 = make_float4(0.f, 0.f, 0.f, 0.f);
    float4 a1 = make_float4(0.f, 0.f, 0.f, 0.f);
    int e = beg;
    for (; e + 2 <= end; e += 2) {
        int s0 = __ldg(g_csrsrc + e);
        int s1 = __ldg(g_csrsrc + e + 1);
        float4 v0 = __ldg(reinterpret_cast<const float4*>(xin + (size_t)s0 * D) + lane);
        float4 v1 = __ldg(reinterpret_cast<const float4*>(xin + (size_t)s1 * D) + lane);
        a0.x += v0.x; a0.y += v0.y; a0.z += v0.z; a0.w += v0.w;
        a1.x += v1.x; a1.y += v1.y; a1.z += v1.z; a1.w += v1.w;
    }
    if (e < end) {
        int s0 = __ldg(g_csrsrc + e);
        float4 v0 = __ldg(reinterpret_cast<const float4*>(xin + (size_t)s0 * D) + lane);
        a0.x += v0.x; a0.y += v0.y; a0.z += v0.z; a0.w += v0.w;
    }
    a0.x += a1.x; a0.y += a1.y; a0.z += a1.z; a0.w += a1.w;
    reinterpret_cast<float4*>(g_agg + (size_t)node * D)[lane] = a0;
}

// ---------------------------------------------------------------------------
// MLP: y = relu(g_agg @ W^T + b); FINAL fuses sigmoid(y . wout + bout).
// Block tile: 32 nodes x 128 features. 256 threads, 4x4 register micro-tile.
// Ws: k-major [128][132] (from pre-transposed g_Wt -> conflict-free staging).
// Xs: n-major [32][129] (odd stride -> scalar x reads are broadcast,
//     conflict-free: 8 distinct banks, 4-way replication).
// Per k: 1 LDS.128 (w) + 4 LDS.32 (x) + 16 FFMA  ->  FMA-pipe bound.
// smem = (128*132 + 32*129)*4 = 84096 B -> 2 blocks/SM.
// ---------------------------------------------------------------------------
template <bool FINAL>
__global__ void __launch_bounds__(256) mlp_kernel(const float* __restrict__ b,
                                                  const float* __restrict__ wout,
                                                  const float* __restrict__ bout,
                                                  float* __restrict__ out) {
    extern __shared__ float sh[];
    float* Ws = sh;                  // [128][132], Ws[k*132+f]
    float* Xs = sh + 128 * 132;      // [32][129],  Xs[n*129+k]
    __shared__ float nodeSum[32];

    const float* __restrict__ Wt = FINAL ? g_W2t : g_W1t;
    const int t = threadIdx.x;
    const int gbase = blockIdx.x * 32;

    // Stage W (k-major, float4 -> float4, conflict-free)
    for (int tau = t; tau < 128 * 32; tau += 256) {
        int k = tau >> 5, f4 = tau & 31;
        float4 w = __ldg(reinterpret_cast<const float4*>(Wt + k * D) + f4);
        *reinterpret_cast<float4*>(Ws + k * 132 + 4 * f4) = w;
    }
    // Stage X (coalesced row reads, scalar smem writes)
    for (int tau = t; tau < 32 * 32; tau += 256) {
        int n = tau >> 5, k4 = tau & 31;
        float4 v = *reinterpret_cast<const float4*>(g_agg + (size_t)(gbase + n) * D + 4 * k4);
        float* p = Xs + n * 129 + 4 * k4;
        p[0] = v.x; p[1] = v.y; p[2] = v.z; p[3] = v.w;
    }

    const int fg = t >> 3, ng = t & 7;
    const int f0 = fg * 4, n0 = ng * 4;
    float bb0 = __ldg(b + f0), bb1 = __ldg(b + f0 + 1);
    float bb2 = __ldg(b + f0 + 2), bb3 = __ldg(b + f0 + 3);
    if (FINAL && t < 32) nodeSum[t] = 0.f;
    __syncthreads();

    float acc[4][4];
#pragma unroll
    for (int i = 0; i < 4; i++)
#pragma unroll
        for (int j = 0; j < 4; j++) acc[i][j] = 0.f;

    const float* wp = Ws + f0;
    const float* xp = Xs + n0 * 129;
#pragma unroll 8
    for (int k = 0; k < 128; k++) {
        float4 w = *reinterpret_cast<const float4*>(wp + k * 132);
        float x0 = xp[k];
        float x1 = xp[129 + k];
        float x2 = xp[258 + k];
        float x3 = xp[387 + k];
        acc[0][0] = fmaf(x0, w.x, acc[0][0]); acc[0][1] = fmaf(x0, w.y, acc[0][1]);
        acc[0][2] = fmaf(x0, w.z, acc[0][2]); acc[0][3] = fmaf(x0, w.w, acc[0][3]);
        acc[1][0] = fmaf(x1, w.x, acc[1][0]); acc[1][1] = fmaf(x1, w.y, acc[1][1]);
        acc[1][2] = fmaf(x1, w.z, acc[1][2]); acc[1][3] = fmaf(x1, w.w, acc[1][3]);
        acc[2][0] = fmaf(x2, w.x, acc[2][0]); acc[2][1] = fmaf(x2, w.y, acc[2][1]);
        acc[2][2] = fmaf(x2, w.z, acc[2][2]); acc[2][3] = fmaf(x2, w.w, acc[2][3]);
        acc[3][0] = fmaf(x3, w.x, acc[3][0]); acc[3][1] = fmaf(x3, w.y, acc[3][1]);
        acc[3][2] = fmaf(x3, w.z, acc[3][2]); acc[3][3] = fmaf(x3, w.w, acc[3][3]);
    }

    if (!FINAL) {
#pragma unroll
        for (int i = 0; i < 4; i++) {
            float4 y;
            y.x = fmaxf(acc[i][0] + bb0, 0.f);
            y.y = fmaxf(acc[i][1] + bb1, 0.f);
            y.z = fmaxf(acc[i][2] + bb2, 0.f);
            y.w = fmaxf(acc[i][3] + bb3, 0.f);
            *reinterpret_cast<float4*>(g_h + (size_t)(gbase + n0 + i) * D + f0) = y;
        }
    } else {
        float wo0 = __ldg(wout + f0),     wo1 = __ldg(wout + f0 + 1);
        float wo2 = __ldg(wout + f0 + 2), wo3 = __ldg(wout + f0 + 3);
#pragma unroll
        for (int i = 0; i < 4; i++) {
            float p = fmaxf(acc[i][0] + bb0, 0.f) * wo0
                    + fmaxf(acc[i][1] + bb1, 0.f) * wo1
                    + fmaxf(acc[i][2] + bb2, 0.f) * wo2
                    + fmaxf(acc[i][3] + bb3, 0.f) * wo3;
            atomicAdd(&nodeSum[n0 + i], p);
        }
        __syncthreads();
        if (t < 32) {
            float s = nodeSum[t] + __ldg(bout);
            out[gbase + t] = 1.f / (1.f + expf(-s));
        }
    }
}

// ---------------------------------------------------------------------------
extern "C" void kernel_launch(void* const* d_in, const int* in_sizes, int n_in,
                              void* d_out, int out_size) {
    const int*   cncpt = (const int*)d_in[0];
    const int*   src   = (const int*)d_in[1];
    const int*   dst   = (const int*)d_in[2];
    const float* emb   = (const float*)d_in[3];
    const float* W1    = (const float*)d_in[4];
    const float* b1    = (const float*)d_in[5];
    const float* W2    = (const float*)d_in[6];
    const float* b2    = (const float*)d_in[7];
    const float* Wout  = (const float*)d_in[8];
    const float* bout  = (const float*)d_in[9];
    float* out = (float*)d_out;

    const int MLP_SMEM = (128 * 132 + 32 * 129) * sizeof(float);  // 84096 B
    cudaFuncSetAttribute(mlp_kernel<false>, cudaFuncAttributeMaxDynamicSharedMemorySize, MLP_SMEM);
    cudaFuncSetAttribute(mlp_kernel<true>,  cudaFuncAttributeMaxDynamicSharedMemorySize, MLP_SMEM);

    const int NODE_BLKS  = (N_NODES + 255) / 256;                 // 391
    const int EDGE_BLKS  = (N_EDGES + 255) / 256;                 // 6250
    const int WARP_BLKS  = (N_NODES * 32 + 255) / 256;            // 12500
    const int MLP_BLKS   = N_NODES / 32;                          // 3125 exact

    // CSR build (reused by both layers) + weight transpose + x0 gather
    transpose_w_kernel<<<(D * D + 255) / 256, 256>>>(W1, W2);
    zero_counts_kernel<<<NODE_BLKS, 256>>>();
    hist_kernel<<<EDGE_BLKS, 256>>>(dst);
    scan1_kernel<<<SCAN_NB, SCAN_BS>>>();
    scan2_kernel<<<1, 32>>>();
    scan3_kernel<<<NODE_BLKS, 256>>>();
    fill_csr_kernel<<<EDGE_BLKS, 256>>>(src, dst);
    gather_x0_kernel<<<WARP_BLKS, 256>>>(cncpt, emb);

    // Layer 1
    agg_kernel<true><<<WARP_BLKS, 256>>>();
    mlp_kernel<false><<<MLP_BLKS, 256, MLP_SMEM>>>(b1, nullptr, nullptr, nullptr);

    // Layer 2 (+ fused output head)
    agg_kernel<false><<<WARP_BLKS, 256>>>();
    mlp_kernel<true><<<MLP_BLKS, 256, MLP_SMEM>>>(b2, Wout, bout, out);

    (void)in_sizes; (void)n_in; (void)out_size;
}

// round 5
// speedup vs baseline: 2.9358x; 1.7922x over previous
#include <cuda_runtime.h>
#include <cuda_bf16.h>
#include <math.h>
#include <stdint.h>

#define N_NODES   100000
#define N_EDGES   1600000
#define D         128
#define SCAN_BS   1024
#define SCAN_NB   ((N_NODES + SCAN_BS - 1) / SCAN_BS)   // 98

// ---------------------------------------------------------------------------
// Scratch (__device__ globals; referenced ONLY from device code)
// ---------------------------------------------------------------------------
__device__ float g_x0 [(size_t)N_NODES * D];   // emb[cncpt[v]]      (51.2 MB)
__device__ float g_agg[(size_t)N_NODES * D];   // aggregation output (51.2 MB)
__device__ float g_h  [(size_t)N_NODES * D];   // layer-1 output     (51.2 MB)
// Pre-split bf16 weights, packed u32 (bf16x2 along k):
// layout [mat(2)][split hi/lo(2)][f(128)][kpair(64)]
__device__ uint32_t g_Wpk[2 * 2 * 128 * 64];
__device__ int g_counts [N_NODES];
__device__ int g_excl   [N_NODES];
__device__ int g_rowptr [N_NODES + 1];
__device__ int g_cursor [N_NODES];
__device__ int g_bsum   [SCAN_NB];
__device__ int g_boff   [SCAN_NB];
__device__ int g_csrsrc [N_EDGES];

// ---------------------------------------------------------------------------
// Weight split prep: g_Wpk <- bf16 hi/lo halves of W1/W2 (error-free split)
// ---------------------------------------------------------------------------
__global__ void wprep_kernel(const float* __restrict__ W1,
                             const float* __restrict__ W2) {
    int i = blockIdx.x * blockDim.x + threadIdx.x;
    if (i >= 2 * 128 * 64) return;
    int mat = i >> 13, rem = i & 8191;
    int f = rem >> 6, p = rem & 63;
    const float* W = mat ? W2 : W1;
    float w0 = __ldg(W + f * D + 2 * p);
    float w1 = __ldg(W + f * D + 2 * p + 1);
    __nv_bfloat162 hi = __floats2bfloat162_rn(w0, w1);
    float r0 = w0 - __bfloat162float(hi.x);
    float r1 = w1 - __bfloat162float(hi.y);
    __nv_bfloat162 lo = __floats2bfloat162_rn(r0, r1);
    uint32_t hiw, low;
    memcpy(&hiw, &hi, 4); memcpy(&low, &lo, 4);
    g_Wpk[((mat * 2 + 0) * 128 + f) * 64 + p] = hiw;
    g_Wpk[((mat * 2 + 1) * 128 + f) * 64 + p] = low;
}

// ---------------------------------------------------------------------------
// CSR build: zero -> histogram -> scan(3) -> fill
// ---------------------------------------------------------------------------
__global__ void zero_counts_kernel() {
    int i = blockIdx.x * blockDim.x + threadIdx.x;
    if (i < N_NODES) g_counts[i] = 0;
}
__global__ void hist_kernel(const int* __restrict__ dst) {
    int e = blockIdx.x * blockDim.x + threadIdx.x;
    if (e < N_EDGES) atomicAdd(&g_counts[__ldg(dst + e)], 1);
}
__global__ void scan1_kernel() {
    __shared__ int s[SCAN_BS];
    int t = threadIdx.x;
    int i = blockIdx.x * SCAN_BS + t;
    int v = (i < N_NODES) ? g_counts[i] : 0;
    s[t] = v;
    __syncthreads();
#pragma unroll
    for (int off = 1; off < SCAN_BS; off <<= 1) {
        int add = (t >= off) ? s[t - off] : 0;
        __syncthreads();
        s[t] += add;
        __syncthreads();
    }
    int incl = s[t];
    if (i < N_NODES) g_excl[i] = incl - v;
    if (t == SCAN_BS - 1) g_bsum[blockIdx.x] = incl;
}
__global__ void scan2_kernel() {
    if (threadIdx.x == 0 && blockIdx.x == 0) {
        int run = 0;
        for (int j = 0; j < SCAN_NB; j++) { g_boff[j] = run; run += g_bsum[j]; }
    }
}
__global__ void scan3_kernel() {
    int i = blockIdx.x * blockDim.x + threadIdx.x;
    if (i < N_NODES) {
        int rp = g_excl[i] + g_boff[i >> 10];
        g_rowptr[i] = rp;
        g_cursor[i] = rp;
    }
    if (i == 0) g_rowptr[N_NODES] = N_EDGES;
}
__global__ void fill_csr_kernel(const int* __restrict__ src,
                                const int* __restrict__ dst) {
    int e = blockIdx.x * blockDim.x + threadIdx.x;
    if (e >= N_EDGES) return;
    int d = __ldg(dst + e);
    int p = atomicAdd(&g_cursor[d], 1);
    g_csrsrc[p] = __ldg(src + e);
}

// ---------------------------------------------------------------------------
// g_x0[v] = emb[cncpt[v]]  (warp per node)
// ---------------------------------------------------------------------------
__global__ void gather_x0_kernel(const int* __restrict__ cncpt,
                                 const float* __restrict__ emb) {
    int node = (blockIdx.x * blockDim.x + threadIdx.x) >> 5;
    if (node >= N_NODES) return;
    int lane = threadIdx.x & 31;
    int c = __ldg(cncpt + node);
    float4 v = __ldg(reinterpret_cast<const float4*>(emb + (size_t)c * D) + lane);
    reinterpret_cast<float4*>(g_x0 + (size_t)node * D)[lane] = v;
}

// ---------------------------------------------------------------------------
// CSR gather-aggregation: g_agg[v] = sum_{e in row v} xin[csrsrc[e]]
// ---------------------------------------------------------------------------
template <bool FIRST>
__global__ void __launch_bounds__(256) agg_kernel() {
    int node = (blockIdx.x * blockDim.x + threadIdx.x) >> 5;
    if (node >= N_NODES) return;
    int lane = threadIdx.x & 31;
    const float* __restrict__ xin = FIRST ? g_x0 : g_h;
    int beg = __ldg(g_rowptr + node);
    int end = __ldg(g_rowptr + node + 1);
    float4 a0 = make_float4(0.f, 0.f, 0.f, 0.f);
    float4 a1 = make_float4(0.f, 0.f, 0.f, 0.f);
    int e = beg;
    for (; e + 2 <= end; e += 2) {
        int s0 = __ldg(g_csrsrc + e);
        int s1 = __ldg(g_csrsrc + e + 1);
        float4 v0 = __ldg(reinterpret_cast<const float4*>(xin + (size_t)s0 * D) + lane);
        float4 v1 = __ldg(reinterpret_cast<const float4*>(xin + (size_t)s1 * D) + lane);
        a0.x += v0.x; a0.y += v0.y; a0.z += v0.z; a0.w += v0.w;
        a1.x += v1.x; a1.y += v1.y; a1.z += v1.z; a1.w += v1.w;
    }
    if (e < end) {
        int s0 = __ldg(g_csrsrc + e);
        float4 v0 = __ldg(reinterpret_cast<const float4*>(xin + (size_t)s0 * D) + lane);
        a0.x += v0.x; a0.y += v0.y; a0.z += v0.z; a0.w += v0.w;
    }
    a0.x += a1.x; a0.y += a1.y; a0.z += a1.z; a0.w += a1.w;
    reinterpret_cast<float4*>(g_agg + (size_t)node * D)[lane] = a0;
}

// ---------------------------------------------------------------------------
// bf16 mma.sync helper (sm_80+ PTX; no 'a'-suffix features)
// ---------------------------------------------------------------------------
__device__ __forceinline__ void mma16816(float* c, const uint32_t* a,
                                         const uint32_t* b) {
    asm volatile(
        "mma.sync.aligned.m16n8k16.row.col.f32.bf16.bf16.f32 "
        "{%0,%1,%2,%3}, {%4,%5,%6,%7}, {%8,%9}, {%0,%1,%2,%3};"
        : "+f"(c[0]), "+f"(c[1]), "+f"(c[2]), "+f"(c[3])
        : "r"(a[0]), "r"(a[1]), "r"(a[2]), "r"(a[3]), "r"(b[0]), "r"(b[1]));
}

// ---------------------------------------------------------------------------
// Tensor-core MLP: y = relu(agg @ W^T + b); FINAL fuses sigmoid(y.wout+bout).
// Error-free bf16 split: y = Xhi@Whi + Xhi@Wlo + Xlo@Whi (fp32 accum).
// CTA = 128 nodes x 128 features, 256 threads, warps in 4x2 grid (32x64 tile).
// Smem tiles stride 68 u32 (136 bf16) -> all fragment LDS conflict-free.
// Dyn smem (u32 words): Xh[128*68] Xl Wh Wl = 4*8704*4B = 139264 B.
// ---------------------------------------------------------------------------
template <bool FINAL>
__global__ void __launch_bounds__(256) mlp_mma_kernel(const float* __restrict__ b,
                                                      const float* __restrict__ wout,
                                                      const float* __restrict__ bout,
                                                      float* __restrict__ out) {
    extern __shared__ uint32_t shw[];
    uint32_t* Xh = shw;                // [128][68]
    uint32_t* Xl = shw + 8704;
    uint32_t* Wh = shw + 2 * 8704;
    uint32_t* Wl = shw + 3 * 8704;
    __shared__ float sb[128];
    __shared__ float swout[128];
    __shared__ float nodeSum[128];

    const int t = threadIdx.x;
    const int wid = t >> 5, lane = t & 31;
    const int gbase = blockIdx.x * 128;

    // Stage W (straight copy of pre-split packed weights)
    {
        const uint32_t* srcH = g_Wpk + (FINAL ? 2 : 0) * 8192;
        const uint32_t* srcL = srcH + 8192;
#pragma unroll
        for (int i = 0; i < 32; i++) {
            int idx = t + 256 * i;            // 8192 total
            int f = idx >> 6, p = idx & 63;
            Wh[f * 68 + p] = __ldg(srcH + idx);
            Wl[f * 68 + p] = __ldg(srcL + idx);
        }
    }
    // Stage X: split g_agg rows into bf16 hi/lo (packed u32 per k-pair)
#pragma unroll
    for (int i = 0; i < 32; i++) {
        int idx = t + 256 * i;                // 8192 total
        int r = idx >> 6, p = idx & 63;
        int node = gbase + r;
        float2 v = make_float2(0.f, 0.f);
        if (node < N_NODES)
            v = *reinterpret_cast<const float2*>(g_agg + (size_t)node * D + 2 * p);
        __nv_bfloat162 hi = __floats2bfloat162_rn(v.x, v.y);
        float r0 = v.x - __bfloat162float(hi.x);
        float r1 = v.y - __bfloat162float(hi.y);
        __nv_bfloat162 lo = __floats2bfloat162_rn(r0, r1);
        uint32_t hiw, low;
        memcpy(&hiw, &hi, 4); memcpy(&low, &lo, 4);
        Xh[r * 68 + p] = hiw;
        Xl[r * 68 + p] = low;
    }
    if (t < 128) {
        sb[t] = __ldg(b + t);
        if (FINAL) { swout[t] = __ldg(wout + t); nodeSum[t] = 0.f; }
    }
    __syncthreads();

    // Warp tile: rows m0..m0+31, cols n0..n0+63
    const int m0 = (wid >> 1) * 32, n0 = (wid & 1) * 64;
    float acc[2][8][4];
#pragma unroll
    for (int mt = 0; mt < 2; mt++)
#pragma unroll
        for (int nt = 0; nt < 8; nt++)
#pragma unroll
            for (int j = 0; j < 4; j++) acc[mt][nt][j] = 0.f;

    const int lq = lane >> 2, lr = lane & 3;
#pragma unroll
    for (int pass = 0; pass < 3; pass++) {
        const uint32_t* Aw = (pass < 2) ? Xh : Xl;
        const uint32_t* Bw = (pass == 1) ? Wl : Wh;
#pragma unroll
        for (int ks = 0; ks < 8; ks++) {
            const int kp = ks * 8 + lr;
            uint32_t a[2][4];
#pragma unroll
            for (int mt = 0; mt < 2; mt++) {
                int r0i = m0 + mt * 16 + lq;
                a[mt][0] = Aw[r0i * 68 + kp];
                a[mt][1] = Aw[(r0i + 8) * 68 + kp];
                a[mt][2] = Aw[r0i * 68 + kp + 4];
                a[mt][3] = Aw[(r0i + 8) * 68 + kp + 4];
            }
            uint32_t bf[8][2];
#pragma unroll
            for (int nt = 0; nt < 8; nt++) {
                int nr = n0 + nt * 8 + lq;
                bf[nt][0] = Bw[nr * 68 + kp];
                bf[nt][1] = Bw[nr * 68 + kp + 4];
            }
#pragma unroll
            for (int mt = 0; mt < 2; mt++)
#pragma unroll
                for (int nt = 0; nt < 8; nt++)
                    mma16816(acc[mt][nt], a[mt], bf[nt]);
        }
    }

    // Epilogue. D frag: c0,c1 -> (row m0+mt*16+lq, col n0+nt*8+lr*2 +{0,1});
    //                   c2,c3 -> row+8, same cols.
    if (!FINAL) {
#pragma unroll
        for (int mt = 0; mt < 2; mt++) {
            int rA = m0 + mt * 16 + lq;
            int nodeA = gbase + rA, nodeB = nodeA + 8;
#pragma unroll
            for (int nt = 0; nt < 8; nt++) {
                int c = n0 + nt * 8 + lr * 2;
                if (nodeA < N_NODES) {
                    float2 y;
                    y.x = fmaxf(acc[mt][nt][0] + sb[c],     0.f);
                    y.y = fmaxf(acc[mt][nt][1] + sb[c + 1], 0.f);
                    *reinterpret_cast<float2*>(g_h + (size_t)nodeA * D + c) = y;
                }
                if (nodeB < N_NODES) {
                    float2 y;
                    y.x = fmaxf(acc[mt][nt][2] + sb[c],     0.f);
                    y.y = fmaxf(acc[mt][nt][3] + sb[c + 1], 0.f);
                    *reinterpret_cast<float2*>(g_h + (size_t)nodeB * D + c) = y;
                }
            }
        }
    } else {
#pragma unroll
        for (int mt = 0; mt < 2; mt++) {
            float pA = 0.f, pB = 0.f;
            int rA = m0 + mt * 16 + lq;
#pragma unroll
            for (int nt = 0; nt < 8; nt++) {
                int c = n0 + nt * 8 + lr * 2;
                pA += fmaxf(acc[mt][nt][0] + sb[c],     0.f) * swout[c]
                    + fmaxf(acc[mt][nt][1] + sb[c + 1], 0.f) * swout[c + 1];
                pB += fmaxf(acc[mt][nt][2] + sb[c],     0.f) * swout[c]
                    + fmaxf(acc[mt][nt][3] + sb[c + 1], 0.f) * swout[c + 1];
            }
            pA += __shfl_xor_sync(0xffffffffu, pA, 1);
            pA += __shfl_xor_sync(0xffffffffu, pA, 2);
            pB += __shfl_xor_sync(0xffffffffu, pB, 1);
            pB += __shfl_xor_sync(0xffffffffu, pB, 2);
            if (lr == 0) {
                atomicAdd(&nodeSum[rA], pA);
                atomicAdd(&nodeSum[rA + 8], pB);
            }
        }
        __syncthreads();
        if (t < 128) {
            int node = gbase + t;
            if (node < N_NODES)
                out[node] = 1.f / (1.f + expf(-(nodeSum[t] + __ldg(bout))));
        }
    }
}

// ---------------------------------------------------------------------------
extern "C" void kernel_launch(void* const* d_in, const int* in_sizes, int n_in,
                              void* d_out, int out_size) {
    const int*   cncpt = (const int*)d_in[0];
    const int*   src   = (const int*)d_in[1];
    const int*   dst   = (const int*)d_in[2];
    const float* emb   = (const float*)d_in[3];
    const float* W1    = (const float*)d_in[4];
    const float* b1    = (const float*)d_in[5];
    const float* W2    = (const float*)d_in[6];
    const float* b2    = (const float*)d_in[7];
    const float* Wout  = (const float*)d_in[8];
    const float* bout  = (const float*)d_in[9];
    float* out = (float*)d_out;

    const int MLP_SMEM = 4 * 8704 * 4;   // 139264 B
    cudaFuncSetAttribute(mlp_mma_kernel<false>, cudaFuncAttributeMaxDynamicSharedMemorySize, MLP_SMEM);
    cudaFuncSetAttribute(mlp_mma_kernel<true>,  cudaFuncAttributeMaxDynamicSharedMemorySize, MLP_SMEM);

    const int NODE_BLKS = (N_NODES + 255) / 256;                 // 391
    const int EDGE_BLKS = (N_EDGES + 255) / 256;                 // 6250
    const int WARP_BLKS = (N_NODES * 32 + 255) / 256;            // 12500
    const int MLP_BLKS  = (N_NODES + 127) / 128;                 // 782

    // Prep: weight split + CSR build + x0 gather
    wprep_kernel<<<64, 256>>>(W1, W2);
    zero_counts_kernel<<<NODE_BLKS, 256>>>();
    hist_kernel<<<EDGE_BLKS, 256>>>(dst);
    scan1_kernel<<<SCAN_NB, SCAN_BS>>>();
    scan2_kernel<<<1, 32>>>();
    scan3_kernel<<<NODE_BLKS, 256>>>();
    fill_csr_kernel<<<EDGE_BLKS, 256>>>(src, dst);
    gather_x0_kernel<<<WARP_BLKS, 256>>>(cncpt, emb);

    // Layer 1
    agg_kernel<true><<<WARP_BLKS, 256>>>();
    mlp_mma_kernel<false><<<MLP_BLKS, 256, MLP_SMEM>>>(b1, nullptr, nullptr, nullptr);

    // Layer 2 (+ fused sigmoid head)
    agg_kernel<false><<<WARP_BLKS, 256>>>();
    mlp_mma_kernel<true><<<MLP_BLKS, 256, MLP_SMEM>>>(b2, Wout, bout, out);

    (void)in_sizes; (void)n_in; (void)out_size;
}

// round 6
// speedup vs baseline: 3.0357x; 1.0340x over previous
#include <cuda_runtime.h>
#include <cuda_bf16.h>
#include <math.h>
#include <stdint.h>

#define N_NODES   100000
#define N_EDGES   1600000
#define D         128
#define SCAN_BS   1024
#define SCAN_NB   ((N_NODES + SCAN_BS - 1) / SCAN_BS)   // 98
#define EDGE_BLKS ((N_EDGES + 255) / 256)               // 6250
#define NODE_BLKS ((N_NODES + 255) / 256)               // 391
#define WARP_BLKS ((N_NODES * 32 + 255) / 256)          // 12500
#define WPREP_BLKS 64                                   // 16384 items / 256

// ---------------------------------------------------------------------------
// Scratch (__device__ globals; referenced ONLY from device code)
// ---------------------------------------------------------------------------
__device__ float g_x0 [(size_t)N_NODES * D];   // emb[cncpt[v]]      (51.2 MB)
__device__ float g_agg[(size_t)N_NODES * D];   // aggregation output (51.2 MB)
__device__ float g_h  [(size_t)N_NODES * D];   // layer-1 output     (51.2 MB)
// Pre-split bf16 weights, packed u32 (bf16x2 along k):
// layout [mat(2)][split hi/lo(2)][f(128)][kpair(64)]
__device__ uint32_t g_Wpk[2 * 2 * 128 * 64];
__device__ int g_counts [N_NODES];
__device__ int g_excl   [N_NODES];
__device__ int g_rowptr [N_NODES + 1];
__device__ int g_cursor [N_NODES];
__device__ int g_bsum   [SCAN_NB];
__device__ int g_csrsrc [N_EDGES];

// ---------------------------------------------------------------------------
// prep: blocks [0,64) split W1/W2 into bf16 hi/lo; blocks [64,..) zero counts
// ---------------------------------------------------------------------------
__global__ void prep_kernel(const float* __restrict__ W1,
                            const float* __restrict__ W2) {
    if (blockIdx.x < WPREP_BLKS) {
        int i = blockIdx.x * blockDim.x + threadIdx.x;   // < 16384
        int mat = i >> 13, rem = i & 8191;
        int f = rem >> 6, p = rem & 63;
        const float* W = mat ? W2 : W1;
        float w0 = __ldg(W + f * D + 2 * p);
        float w1 = __ldg(W + f * D + 2 * p + 1);
        __nv_bfloat162 hi = __floats2bfloat162_rn(w0, w1);
        float r0 = w0 - __bfloat162float(hi.x);
        float r1 = w1 - __bfloat162float(hi.y);
        __nv_bfloat162 lo = __floats2bfloat162_rn(r0, r1);
        uint32_t hiw, low;
        memcpy(&hiw, &hi, 4); memcpy(&low, &lo, 4);
        g_Wpk[((mat * 2 + 0) * 128 + f) * 64 + p] = hiw;
        g_Wpk[((mat * 2 + 1) * 128 + f) * 64 + p] = low;
    } else {
        int i = (blockIdx.x - WPREP_BLKS) * blockDim.x + threadIdx.x;
        if (i < N_NODES) g_counts[i] = 0;
    }
}

// ---------------------------------------------------------------------------
// hist + gather_x0 merged (independent workloads, overlap LTS vs DRAM):
//   blocks [0, EDGE_BLKS): histogram of dst
//   blocks [EDGE_BLKS, +WARP_BLKS): g_x0[v] = emb[cncpt[v]] (warp per node)
// ---------------------------------------------------------------------------
__global__ void hist_gather_kernel(const int* __restrict__ dst,
                                   const int* __restrict__ cncpt,
                                   const float* __restrict__ emb) {
    if (blockIdx.x < EDGE_BLKS) {
        int e = blockIdx.x * blockDim.x + threadIdx.x;
        if (e < N_EDGES) atomicAdd(&g_counts[__ldg(dst + e)], 1);
    } else {
        int node = ((blockIdx.x - EDGE_BLKS) * blockDim.x + threadIdx.x) >> 5;
        if (node >= N_NODES) return;
        int lane = threadIdx.x & 31;
        int c = __ldg(cncpt + node);
        float4 v = __ldg(reinterpret_cast<const float4*>(emb + (size_t)c * D) + lane);
        reinterpret_cast<float4*>(g_x0 + (size_t)node * D)[lane] = v;
    }
}

// ---------------------------------------------------------------------------
// scan1: per-1024-block exclusive scan via warp shuffles
// ---------------------------------------------------------------------------
__global__ void scan1_kernel() {
    __shared__ int wsum[32];
    const int t = threadIdx.x, lane = t & 31, wid = t >> 5;
    int i = blockIdx.x * SCAN_BS + t;
    int v = (i < N_NODES) ? g_counts[i] : 0;
    // warp inclusive scan
    int s = v;
#pragma unroll
    for (int o = 1; o < 32; o <<= 1) {
        int y = __shfl_up_sync(0xffffffffu, s, o);
        if (lane >= o) s += y;
    }
    if (lane == 31) wsum[wid] = s;
    __syncthreads();
    if (wid == 0) {
        int ws = wsum[lane];
#pragma unroll
        for (int o = 1; o < 32; o <<= 1) {
            int y = __shfl_up_sync(0xffffffffu, ws, o);
            if (lane >= o) ws += y;
        }
        wsum[lane] = ws;
    }
    __syncthreads();
    int incl = s + (wid ? wsum[wid - 1] : 0);
    if (i < N_NODES) g_excl[i] = incl - v;
    if (t == SCAN_BS - 1) g_bsum[blockIdx.x] = incl;
}

// ---------------------------------------------------------------------------
// scan23: each block j computes prefix(bsum[0..j)) with a warp reduce, then
// writes rowptr/cursor for its 1024 nodes.
// ---------------------------------------------------------------------------
__global__ void scan23_kernel() {
    __shared__ int pref;
    const int t = threadIdx.x;
    const int j = blockIdx.x;
    if (t < 32) {
        int s = 0;
        for (int k = t; k < j; k += 32) s += g_bsum[k];
#pragma unroll
        for (int o = 16; o; o >>= 1) s += __shfl_xor_sync(0xffffffffu, s, o);
        if (t == 0) pref = s;
    }
    __syncthreads();
    int i = j * SCAN_BS + t;
    if (i < N_NODES) {
        int rp = g_excl[i] + pref;
        g_rowptr[i] = rp;
        g_cursor[i] = rp;
    }
    if (i == 0) g_rowptr[N_NODES] = N_EDGES;
}

__global__ void fill_csr_kernel(const int* __restrict__ src,
                                const int* __restrict__ dst) {
    int e = blockIdx.x * blockDim.x + threadIdx.x;
    if (e >= N_EDGES) return;
    int d = __ldg(dst + e);
    int p = atomicAdd(&g_cursor[d], 1);
    g_csrsrc[p] = __ldg(src + e);
}

// ---------------------------------------------------------------------------
// CSR gather-aggregation, shfl index distribution:
// one coalesced csrsrc load per <=32 edges, broadcast via shfl; row loads
// issue back-to-back (no per-edge index dependency on the critical path).
// ---------------------------------------------------------------------------
template <bool FIRST>
__global__ void __launch_bounds__(256) agg_kernel() {
    int node = (blockIdx.x * blockDim.x + threadIdx.x) >> 5;
    if (node >= N_NODES) return;
    int lane = threadIdx.x & 31;
    const float* __restrict__ xin = FIRST ? g_x0 : g_h;
    int beg = __ldg(g_rowptr + node);
    int end = __ldg(g_rowptr + node + 1);

    float4 a0 = make_float4(0.f, 0.f, 0.f, 0.f);
    float4 a1 = make_float4(0.f, 0.f, 0.f, 0.f);
    int e = beg;
    while (e < end) {
        int n = end - e; if (n > 32) n = 32;
        int idx = (lane < n) ? __ldg(g_csrsrc + e + lane) : 0;
        int j = 0;
        for (; j + 2 <= n; j += 2) {
            int s0 = __shfl_sync(0xffffffffu, idx, j);
            int s1 = __shfl_sync(0xffffffffu, idx, j + 1);
            float4 v0 = __ldg(reinterpret_cast<const float4*>(xin + (size_t)s0 * D) + lane);
            float4 v1 = __ldg(reinterpret_cast<const float4*>(xin + (size_t)s1 * D) + lane);
            a0.x += v0.x; a0.y += v0.y; a0.z += v0.z; a0.w += v0.w;
            a1.x += v1.x; a1.y += v1.y; a1.z += v1.z; a1.w += v1.w;
        }
        if (j < n) {
            int s0 = __shfl_sync(0xffffffffu, idx, j);
            float4 v0 = __ldg(reinterpret_cast<const float4*>(xin + (size_t)s0 * D) + lane);
            a0.x += v0.x; a0.y += v0.y; a0.z += v0.z; a0.w += v0.w;
        }
        e += n;
    }
    a0.x += a1.x; a0.y += a1.y; a0.z += a1.z; a0.w += a1.w;
    reinterpret_cast<float4*>(g_agg + (size_t)node * D)[lane] = a0;
}

// ---------------------------------------------------------------------------
// bf16 mma.sync helper (sm_80+ PTX; no 'a'-suffix features)
// ---------------------------------------------------------------------------
__device__ __forceinline__ void mma16816(float* c, const uint32_t* a,
                                         const uint32_t* b) {
    asm volatile(
        "mma.sync.aligned.m16n8k16.row.col.f32.bf16.bf16.f32 "
        "{%0,%1,%2,%3}, {%4,%5,%6,%7}, {%8,%9}, {%0,%1,%2,%3};"
        : "+f"(c[0]), "+f"(c[1]), "+f"(c[2]), "+f"(c[3])
        : "r"(a[0]), "r"(a[1]), "r"(a[2]), "r"(a[3]), "r"(b[0]), "r"(b[1]));
}

// ---------------------------------------------------------------------------
// Tensor-core MLP: y = relu(agg @ W^T + b); FINAL fuses sigmoid(y.wout+bout).
// Error-free bf16 split: y = Xhi@Whi + Xhi@Wlo + Xlo@Whi (fp32 accum).
// CTA = 128 nodes x 128 features, 256 threads, warps in 4x2 grid (32x64 tile).
// Smem tiles stride 68 u32 (136 bf16) -> all fragment LDS conflict-free.
// ---------------------------------------------------------------------------
template <bool FINAL>
__global__ void __launch_bounds__(256) mlp_mma_kernel(const float* __restrict__ b,
                                                      const float* __restrict__ wout,
                                                      const float* __restrict__ bout,
                                                      float* __restrict__ out) {
    extern __shared__ uint32_t shw[];
    uint32_t* Xh = shw;                // [128][68]
    uint32_t* Xl = shw + 8704;
    uint32_t* Wh = shw + 2 * 8704;
    uint32_t* Wl = shw + 3 * 8704;
    __shared__ float sb[128];
    __shared__ float swout[128];
    __shared__ float nodeSum[128];

    const int t = threadIdx.x;
    const int wid = t >> 5, lane = t & 31;
    const int gbase = blockIdx.x * 128;

    // Stage W (straight copy of pre-split packed weights)
    {
        const uint32_t* srcH = g_Wpk + (FINAL ? 2 : 0) * 8192;
        const uint32_t* srcL = srcH + 8192;
#pragma unroll
        for (int i = 0; i < 32; i++) {
            int idx = t + 256 * i;            // 8192 total
            int f = idx >> 6, p = idx & 63;
            Wh[f * 68 + p] = __ldg(srcH + idx);
            Wl[f * 68 + p] = __ldg(srcL + idx);
        }
    }
    // Stage X: split g_agg rows into bf16 hi/lo (packed u32 per k-pair)
#pragma unroll
    for (int i = 0; i < 32; i++) {
        int idx = t + 256 * i;                // 8192 total
        int r = idx >> 6, p = idx & 63;
        int node = gbase + r;
        float2 v = make_float2(0.f, 0.f);
        if (node < N_NODES)
            v = *reinterpret_cast<const float2*>(g_agg + (size_t)node * D + 2 * p);
        __nv_bfloat162 hi = __floats2bfloat162_rn(v.x, v.y);
        float r0 = v.x - __bfloat162float(hi.x);
        float r1 = v.y - __bfloat162float(hi.y);
        __nv_bfloat162 lo = __floats2bfloat162_rn(r0, r1);
        uint32_t hiw, low;
        memcpy(&hiw, &hi, 4); memcpy(&low, &lo, 4);
        Xh[r * 68 + p] = hiw;
        Xl[r * 68 + p] = low;
    }
    if (t < 128) {
        sb[t] = __ldg(b + t);
        if (FINAL) { swout[t] = __ldg(wout + t); nodeSum[t] = 0.f; }
    }
    __syncthreads();

    // Warp tile: rows m0..m0+31, cols n0..n0+63
    const int m0 = (wid >> 1) * 32, n0 = (wid & 1) * 64;
    float acc[2][8][4];
#pragma unroll
    for (int mt = 0; mt < 2; mt++)
#pragma unroll
        for (int nt = 0; nt < 8; nt++)
#pragma unroll
            for (int j = 0; j < 4; j++) acc[mt][nt][j] = 0.f;

    const int lq = lane >> 2, lr = lane & 3;
#pragma unroll
    for (int pass = 0; pass < 3; pass++) {
        const uint32_t* Aw = (pass < 2) ? Xh : Xl;
        const uint32_t* Bw = (pass == 1) ? Wl : Wh;
#pragma unroll
        for (int ks = 0; ks < 8; ks++) {
            const int kp = ks * 8 + lr;
            uint32_t a[2][4];
#pragma unroll
            for (int mt = 0; mt < 2; mt++) {
                int r0i = m0 + mt * 16 + lq;
                a[mt][0] = Aw[r0i * 68 + kp];
                a[mt][1] = Aw[(r0i + 8) * 68 + kp];
                a[mt][2] = Aw[r0i * 68 + kp + 4];
                a[mt][3] = Aw[(r0i + 8) * 68 + kp + 4];
            }
            uint32_t bf[8][2];
#pragma unroll
            for (int nt = 0; nt < 8; nt++) {
                int nr = n0 + nt * 8 + lq;
                bf[nt][0] = Bw[nr * 68 + kp];
                bf[nt][1] = Bw[nr * 68 + kp + 4];
            }
#pragma unroll
            for (int mt = 0; mt < 2; mt++)
#pragma unroll
                for (int nt = 0; nt < 8; nt++)
                    mma16816(acc[mt][nt], a[mt], bf[nt]);
        }
    }

    // Epilogue. D frag: c0,c1 -> (row m0+mt*16+lq, col n0+nt*8+lr*2 +{0,1});
    //                   c2,c3 -> row+8, same cols.
    if (!FINAL) {
#pragma unroll
        for (int mt = 0; mt < 2; mt++) {
            int rA = m0 + mt * 16 + lq;
            int nodeA = gbase + rA, nodeB = nodeA + 8;
#pragma unroll
            for (int nt = 0; nt < 8; nt++) {
                int c = n0 + nt * 8 + lr * 2;
                if (nodeA < N_NODES) {
                    float2 y;
                    y.x = fmaxf(acc[mt][nt][0] + sb[c],     0.f);
                    y.y = fmaxf(acc[mt][nt][1] + sb[c + 1], 0.f);
                    *reinterpret_cast<float2*>(g_h + (size_t)nodeA * D + c) = y;
                }
                if (nodeB < N_NODES) {
                    float2 y;
                    y.x = fmaxf(acc[mt][nt][2] + sb[c],     0.f);
                    y.y = fmaxf(acc[mt][nt][3] + sb[c + 1], 0.f);
                    *reinterpret_cast<float2*>(g_h + (size_t)nodeB * D + c) = y;
                }
            }
        }
    } else {
#pragma unroll
        for (int mt = 0; mt < 2; mt++) {
            float pA = 0.f, pB = 0.f;
            int rA = m0 + mt * 16 + lq;
#pragma unroll
            for (int nt = 0; nt < 8; nt++) {
                int c = n0 + nt * 8 + lr * 2;
                pA += fmaxf(acc[mt][nt][0] + sb[c],     0.f) * swout[c]
                    + fmaxf(acc[mt][nt][1] + sb[c + 1], 0.f) * swout[c + 1];
                pB += fmaxf(acc[mt][nt][2] + sb[c],     0.f) * swout[c]
                    + fmaxf(acc[mt][nt][3] + sb[c + 1], 0.f) * swout[c + 1];
            }
            pA += __shfl_xor_sync(0xffffffffu, pA, 1);
            pA += __shfl_xor_sync(0xffffffffu, pA, 2);
            pB += __shfl_xor_sync(0xffffffffu, pB, 1);
            pB += __shfl_xor_sync(0xffffffffu, pB, 2);
            if (lr == 0) {
                atomicAdd(&nodeSum[rA], pA);
                atomicAdd(&nodeSum[rA + 8], pB);
            }
        }
        __syncthreads();
        if (t < 128) {
            int node = gbase + t;
            if (node < N_NODES)
                out[node] = 1.f / (1.f + expf(-(nodeSum[t] + __ldg(bout))));
        }
    }
}

// ---------------------------------------------------------------------------
extern "C" void kernel_launch(void* const* d_in, const int* in_sizes, int n_in,
                              void* d_out, int out_size) {
    const int*   cncpt = (const int*)d_in[0];
    const int*   src   = (const int*)d_in[1];
    const int*   dst   = (const int*)d_in[2];
    const float* emb   = (const float*)d_in[3];
    const float* W1    = (const float*)d_in[4];
    const float* b1    = (const float*)d_in[5];
    const float* W2    = (const float*)d_in[6];
    const float* b2    = (const float*)d_in[7];
    const float* Wout  = (const float*)d_in[8];
    const float* bout  = (const float*)d_in[9];
    float* out = (float*)d_out;

    const int MLP_SMEM = 4 * 8704 * 4;   // 139264 B
    cudaFuncSetAttribute(mlp_mma_kernel<false>, cudaFuncAttributeMaxDynamicSharedMemorySize, MLP_SMEM);
    cudaFuncSetAttribute(mlp_mma_kernel<true>,  cudaFuncAttributeMaxDynamicSharedMemorySize, MLP_SMEM);

    const int MLP_BLKS = (N_NODES + 127) / 128;   // 782

    // Prep (wsplit + zero counts), then CSR build overlapped with x0 gather
    prep_kernel<<<WPREP_BLKS + NODE_BLKS, 256>>>(W1, W2);
    hist_gather_kernel<<<EDGE_BLKS + WARP_BLKS, 256>>>(dst, cncpt, emb);
    scan1_kernel<<<SCAN_NB, SCAN_BS>>>();
    scan23_kernel<<<SCAN_NB, SCAN_BS>>>();
    fill_csr_kernel<<<EDGE_BLKS, 256>>>(src, dst);

    // Layer 1
    agg_kernel<true><<<WARP_BLKS, 256>>>();
    mlp_mma_kernel<false><<<MLP_BLKS, 256, MLP_SMEM>>>(b1, nullptr, nullptr, nullptr);

    // Layer 2 (+ fused sigmoid head)
    agg_kernel<false><<<WARP_BLKS, 256>>>();
    mlp_mma_kernel<true><<<MLP_BLKS, 256, MLP_SMEM>>>(b2, Wout, bout, out);

    (void)in_sizes; (void)n_in; (void)out_size;
}